// round 5
// baseline (speedup 1.0000x reference)
#include <cuda_runtime.h>
#include <cuda_bf16.h>
#include <math_constants.h>
#include <cstdint>

#define NUM_E 8192
#define DIM   512
#define BATCH 8
#define LSEQ  4096
#define NTOK  (BATCH * LSEQ)          // 32768
#define QELEMS ((size_t)BATCH * DIM * LSEQ)  // 16777216
#define CAP   32
#define TAU   4e-4f

// ---------------- scratch (device globals; no runtime allocation) ----------
__device__ __align__(256) float         g_xT[(size_t)NTOK * DIM];
__device__ __align__(256) __nv_bfloat16 g_xbf[(size_t)NTOK * DIM];
__device__ __align__(256) float         g_codebook[(size_t)NUM_E * DIM];
__device__ __align__(256) __nv_bfloat16 g_cbf[(size_t)NUM_E * DIM];
__device__ float  g_xnorm[NTOK];
__device__ float  g_cnorm[NUM_E];
__device__ int    g_cand[(size_t)NTOK * CAP];
__device__ int    g_cnt[NTOK];
__device__ int    g_argmin[NTOK];
__device__ double g_loss;

// ---------------- PTX helpers (baseline ISA only; no tcgen05) ---------------
__device__ __forceinline__ uint32_t smem_u32(const void* p) {
    uint32_t a;
    asm("{ .reg .u64 t; cvta.to.shared.u64 t, %1; cvt.u32.u64 %0, t; }"
        : "=r"(a) : "l"(p));
    return a;
}
__device__ __forceinline__ void cp16(uint32_t dst, const void* src) {
    asm volatile("cp.async.cg.shared.global [%0], [%1], 16;" :: "r"(dst), "l"(src));
}
#define CP_COMMIT() asm volatile("cp.async.commit_group;" ::: "memory")
#define CP_WAIT1()  asm volatile("cp.async.wait_group 1;" ::: "memory")

__device__ __forceinline__ void ldm_x4(uint32_t& r0, uint32_t& r1, uint32_t& r2,
                                       uint32_t& r3, uint32_t addr) {
    asm volatile("ldmatrix.sync.aligned.m8n8.x4.shared.b16 {%0,%1,%2,%3}, [%4];"
                 : "=r"(r0), "=r"(r1), "=r"(r2), "=r"(r3) : "r"(addr));
}
__device__ __forceinline__ void mma_bf16(float& c0, float& c1, float& c2, float& c3,
                                         uint32_t a0, uint32_t a1, uint32_t a2,
                                         uint32_t a3, uint32_t b0, uint32_t b1) {
    asm volatile("mma.sync.aligned.m16n8k16.row.col.f32.bf16.bf16.f32 "
                 "{%0,%1,%2,%3}, {%4,%5,%6,%7}, {%8,%9}, {%0,%1,%2,%3};"
                 : "+f"(c0), "+f"(c1), "+f"(c2), "+f"(c3)
                 : "r"(a0), "r"(a1), "r"(a2), "r"(a3), "r"(b0), "r"(b1));
}
// order-preserving float<->uint map for unsigned atomicMin
__device__ __forceinline__ uint32_t fmap(float f) {
    uint32_t u = __float_as_uint(f);
    return (u & 0x80000000u) ? ~u : (u | 0x80000000u);
}
__device__ __forceinline__ float funmap(uint32_t u) {
    return __uint_as_float((u & 0x80000000u) ? (u & 0x7FFFFFFFu) : ~u);
}

// ---------------------------------------------------------------------------
__global__ void zero_loss_kernel() { g_loss = 0.0; }

// inputs [B, D, L] -> g_xT / g_xbf [(b*L + l), d]
__global__ void transpose_kernel(const float* __restrict__ in) {
    __shared__ float tile[32][33];
    int b  = blockIdx.z;
    int d0 = blockIdx.y * 32;
    int l0 = blockIdx.x * 32;
    int tx = threadIdx.x, ty = threadIdx.y;
    const float* src = in + (size_t)b * DIM * LSEQ;
#pragma unroll
    for (int i = 0; i < 4; i++)
        tile[ty + i * 8][tx] = src[(size_t)(d0 + ty + i * 8) * LSEQ + l0 + tx];
    __syncthreads();
#pragma unroll
    for (int i = 0; i < 4; i++) {
        int l = l0 + ty + i * 8;
        float v = tile[tx][ty + i * 8];
        size_t idx = (size_t)(b * LSEQ + l) * DIM + d0 + tx;
        g_xT[idx] = v;
        g_xbf[idx] = __float2bfloat16(v);
    }
}

// codebook[k][d] = sum_j emb[k][j] * proj[d][j]  (128x128 tile, 8x8/thread)
__global__ __launch_bounds__(256, 2) void codebook_gemm_kernel(
    const float* __restrict__ E, const float* __restrict__ P) {
    __shared__ float As[8][128];
    __shared__ float Bs[8][128];
    int tid = threadIdx.x;
    int ty = tid >> 4, tx = tid & 15;
    int k0 = blockIdx.y * 128;
    int d0 = blockIdx.x * 128;
    int srow = tid >> 2;
    int scol = (tid & 3) * 2;
    float acc[8][8];
#pragma unroll
    for (int i = 0; i < 8; i++)
#pragma unroll
        for (int j = 0; j < 8; j++) acc[i][j] = 0.f;

    for (int j0 = 0; j0 < DIM; j0 += 8) {
#pragma unroll
        for (int i = 0; i < 2; i++) {
            int m = srow + i * 64;
            float2 av = *(const float2*)&E[(size_t)(k0 + m) * DIM + j0 + scol];
            float2 bv = *(const float2*)&P[(size_t)(d0 + m) * DIM + j0 + scol];
            As[scol][m] = av.x; As[scol + 1][m] = av.y;
            Bs[scol][m] = bv.x; Bs[scol + 1][m] = bv.y;
        }
        __syncthreads();
#pragma unroll
        for (int j = 0; j < 8; j++) {
            float a[8], bb[8];
#pragma unroll
            for (int i = 0; i < 8; i++) a[i]  = As[j][ty * 8 + i];
#pragma unroll
            for (int i = 0; i < 8; i++) bb[i] = Bs[j][tx * 8 + i];
#pragma unroll
            for (int i = 0; i < 8; i++)
#pragma unroll
                for (int jj = 0; jj < 8; jj++) acc[i][jj] += a[i] * bb[jj];
        }
        __syncthreads();
    }
#pragma unroll
    for (int i = 0; i < 8; i++)
#pragma unroll
        for (int jj = 0; jj < 8; jj++) {
            float v = acc[i][jj];
            size_t idx = (size_t)(k0 + ty * 8 + i) * DIM + d0 + tx * 8 + jj;
            g_codebook[idx] = v;
            g_cbf[idx] = __float2bfloat16(v);
        }
}

__global__ void rownorm_kernel(int which) {
    int warp = (blockIdx.x * blockDim.x + threadIdx.x) >> 5;
    int lane = threadIdx.x & 31;
    int rows = which ? NUM_E : NTOK;
    if (warp >= rows) return;
    const float* r = (which ? g_codebook : g_xT) + (size_t)warp * DIM;
    float s = 0.f;
#pragma unroll
    for (int i = 0; i < DIM / 32; i++) { float v = r[lane + i * 32]; s += v * v; }
#pragma unroll
    for (int o = 16; o; o >>= 1) s += __shfl_down_sync(0xffffffffu, s, o);
    if (lane == 0) (which ? g_cnorm : g_xnorm)[warp] = s;
}

// ------------------- HMMA (mma.sync) candidate-filter kernel ----------------
// smem layout (bytes from dynamic base):
#define OFF_X    0          // 128 rows x 1024B (swizzled)            131072
#define OFF_C    131072     // 3 x 16384 (128 codes x 128B, swizzled)  49152
#define OFF_CAND 180224     // 128 x CAP x 4                           16384
#define OFF_CNT  196608     // 128 x 4
#define OFF_RMIN 197120     // 128 x 4
#define OFF_CNS  197632     // 128 x 4
#define SMEM_REQ 198144

__device__ __forceinline__ void prefetch_stage(int s, int tid, uint32_t cbase) {
    if (s < 512) {
        int nc = s >> 3, dc = s & 7, buf = s % 3;
        int row = tid >> 1, half = tid & 1;
        const char* srow = (const char*)g_cbf
            + (size_t)(nc * 128 + row) * 1024 + dc * 128 + half * 64;
        uint32_t drow = cbase + buf * 16384 + row * 128;
        uint32_t xr = (uint32_t)((row & 7) << 4);
#pragma unroll
        for (int i = 0; i < 4; i++) {
            uint32_t b = half * 64 + i * 16;
            cp16(drow + (b ^ xr), srow + i * 16);
        }
    }
    CP_COMMIT();
}

__global__ __launch_bounds__(256, 1) void filter_kernel() {
    extern __shared__ __align__(16) char sm[];
    uint32_t smb = smem_u32(sm);
    int tid  = threadIdx.x;
    int wid  = tid >> 5;
    int lane = tid & 31;
    int m0   = blockIdx.x * 128;
    int mw = wid & 1;          // M-split: 2 x 64
    int nw = wid >> 1;         // N-split: 4 x 32

    uint32_t xbase = smb + OFF_X;
    uint32_t cbase = smb + OFF_C;
    int*      cand_s = (int*)(sm + OFF_CAND);
    uint32_t* cnt_s  = (uint32_t*)(sm + OFF_CNT);
    uint32_t* rmin_s = (uint32_t*)(sm + OFF_RMIN);
    float*    cn_s   = (float*)(sm + OFF_CNS);

    if (tid < 128) { cnt_s[tid] = 0; rmin_s[tid] = 0xFF800000u; } // map(+inf)

    // ---- stage X tile (swizzled bf16) ----
    {
        int row = tid >> 1, half = tid & 1;
        const uint4* srow = (const uint4*)((const char*)g_xbf
                            + (size_t)(m0 + row) * 1024 + half * 512);
        char* drow = sm + OFF_X + row * 1024;
        uint32_t xr = (uint32_t)((row & 7) << 4);
#pragma unroll
        for (int j = 0; j < 32; j++) {
            uint4 v = srow[j];
            uint32_t b = half * 512 + j * 16;
            *(uint4*)(drow + (b ^ xr)) = v;
        }
    }

    // ---- precomputed ldmatrix addressing ----
    // A (x4): lanes 0-7 rows0-7/klo, 8-15 rows8-15/klo, 16-23 rows0-7/khi, 24-31 rows8-15/khi
    uint32_t aRow[4], aXor[4];
#pragma unroll
    for (int mf = 0; mf < 4; mf++) {
        int r = mw * 64 + mf * 16 + (lane & 15);
        aRow[mf] = (uint32_t)(r * 1024);
        aXor[mf] = (uint32_t)((r & 7) << 4);
    }
    uint32_t aK = ((lane >> 4) & 1) * 16;
    // B (x4): lanes0-7 n0-7/klo, 8-15 n0-7/khi, 16-23 n8-15/klo, 24-31 n8-15/khi
    uint32_t bRow[2], bXor[2];
    {
        int n16 = (lane & 7) + ((lane >> 4) & 1) * 8;
#pragma unroll
        for (int g = 0; g < 2; g++) {
            int r = nw * 32 + g * 16 + n16;
            bRow[g] = (uint32_t)(r * 128);
            bXor[g] = (uint32_t)((r & 7) << 4);
        }
    }
    uint32_t bK = ((lane >> 3) & 1) * 16;

    float accs[4][4][4];
#pragma unroll
    for (int mf = 0; mf < 4; mf++)
#pragma unroll
        for (int nf = 0; nf < 4; nf++)
#pragma unroll
            for (int v = 0; v < 4; v++) accs[mf][nf][v] = 0.f;

    prefetch_stage(0, tid, cbase);
    prefetch_stage(1, tid, cbase);
    __syncthreads();   // X tile + init visible

    for (int s = 0; s < 512; s++) {
        int nc = s >> 3, dc = s & 7;
        CP_WAIT1();
        __syncthreads();
        if (dc == 0 && tid < 128) cn_s[tid] = __ldg(&g_cnorm[nc * 128 + tid]);
        prefetch_stage(s + 2, tid, cbase);

        uint32_t cb = cbase + (uint32_t)(s % 3) * 16384;
#pragma unroll
        for (int ks = 0; ks < 4; ks++) {
            uint32_t a[4][4];
            uint32_t abyte = (uint32_t)(dc * 128 + ks * 32) + aK;
#pragma unroll
            for (int mf = 0; mf < 4; mf++)
                ldm_x4(a[mf][0], a[mf][1], a[mf][2], a[mf][3],
                       xbase + aRow[mf] + (abyte ^ aXor[mf]));
            uint32_t b[2][4];
            uint32_t bbyte = (uint32_t)(ks * 32) + bK;
#pragma unroll
            for (int g = 0; g < 2; g++)
                ldm_x4(b[g][0], b[g][1], b[g][2], b[g][3],
                       cb + bRow[g] + (bbyte ^ bXor[g]));
#pragma unroll
            for (int mf = 0; mf < 4; mf++)
#pragma unroll
                for (int nf = 0; nf < 4; nf++) {
                    uint32_t b0 = b[nf >> 1][(nf & 1) * 2];
                    uint32_t b1 = b[nf >> 1][(nf & 1) * 2 + 1];
                    mma_bf16(accs[mf][nf][0], accs[mf][nf][1],
                             accs[mf][nf][2], accs[mf][nf][3],
                             a[mf][0], a[mf][1], a[mf][2], a[mf][3], b0, b1);
                }
        }

        if (dc == 7) {
            // epilogue: sv = cn - 2*acc, shared running-min + candidate append
#pragma unroll
            for (int mf = 0; mf < 4; mf++) {
#pragma unroll
                for (int half = 0; half < 2; half++) {
                    int r = mw * 64 + mf * 16 + (lane >> 2) + half * 8;
                    float rm = funmap(rmin_s[r]);
#pragma unroll
                    for (int nf = 0; nf < 4; nf++) {
                        int c = nw * 32 + nf * 8 + (lane & 3) * 2;
#pragma unroll
                        for (int e = 0; e < 2; e++) {
                            float sv = fmaf(-2.0f, accs[mf][nf][half * 2 + e],
                                            cn_s[c + e]);
                            if (sv < rm) {
                                rm = sv;
                                atomicMin(&rmin_s[r], fmap(sv));
                            }
                            if (sv <= rm + TAU) {
                                uint32_t slot = atomicAdd(&cnt_s[r], 1u);
                                if (slot < CAP)
                                    cand_s[r * CAP + slot] = nc * 128 + c + e;
                            }
                        }
                        accs[mf][nf][half * 2 + 0] = 0.f;
                        accs[mf][nf][half * 2 + 1] = 0.f;
                    }
                }
            }
        }
    }

    __syncthreads();
    if (tid < 128) {
        uint32_t n = cnt_s[tid];
        g_cnt[m0 + tid] = (n > CAP) ? -1 : (int)n;
        int nn = n > CAP ? CAP : (int)n;
        for (int i = 0; i < nn; i++)
            g_cand[(size_t)(m0 + tid) * CAP + i] = cand_s[tid * CAP + i];
    }
}

// exact fp32 rescore (sequential FMA chain); -1 count => full-scan fallback
__global__ __launch_bounds__(256) void rescore_kernel() {
    int t = blockIdx.x * 256 + threadIdx.x;
    float xn = g_xnorm[t];
    int n = g_cnt[t];
    const float4* xr = (const float4*)(g_xT + (size_t)t * DIM);
    float best = CUDART_INF_F;
    int bi = 0;
    int total = (n < 0) ? NUM_E : n;
    for (int i = 0; i < total; i++) {
        int k = (n < 0) ? i : g_cand[(size_t)t * CAP + i];
        const float4* cr = (const float4*)(g_codebook + (size_t)k * DIM);
        float acc = 0.f;
#pragma unroll 8
        for (int v = 0; v < DIM / 4; v++) {
            float4 a = xr[v], b = cr[v];
            acc = fmaf(a.x, b.x, acc);
            acc = fmaf(a.y, b.y, acc);
            acc = fmaf(a.z, b.z, acc);
            acc = fmaf(a.w, b.w, acc);
        }
        float dv = (xn + g_cnorm[k]) - 2.0f * acc;
        if (dv < best || (dv == best && k < bi)) { best = dv; bi = k; }
    }
    g_argmin[t] = bi;
}

// gather codebook rows, write quantized [B,D,L], indices-as-float, loss accum
__global__ __launch_bounds__(256) void gather_out_kernel(
    const float* __restrict__ in, float* __restrict__ out) {
    __shared__ float qs[16][513];
    __shared__ int sidx[16];
    __shared__ double wsum[8];
    int t0 = blockIdx.x * 16;
    int tid = threadIdx.x;
    if (tid < 16) sidx[tid] = g_argmin[t0 + tid];
    __syncthreads();
#pragma unroll
    for (int i = 0; i < 8; i++) {
        int e = tid + i * 256;
        int tok = e >> 7, d4 = e & 127;
        float4 v = *(const float4*)&g_codebook[(size_t)sidx[tok] * DIM + d4 * 4];
        qs[tok][d4 * 4]     = v.x;
        qs[tok][d4 * 4 + 1] = v.y;
        qs[tok][d4 * 4 + 2] = v.z;
        qs[tok][d4 * 4 + 3] = v.w;
    }
    __syncthreads();
    int b  = t0 / LSEQ;
    int l0 = t0 % LSEQ;
    const float* src = in  + (size_t)b * DIM * LSEQ;
    float*       dst = out + (size_t)b * DIM * LSEQ;
    double ls = 0.0;
#pragma unroll
    for (int i = 0; i < 32; i++) {
        int e = tid + i * 256;
        int d = e >> 4, l = e & 15;
        float q = qs[l][d];
        float x = src[(size_t)d * LSEQ + l0 + l];
        float dd = q - x;
        dst[(size_t)d * LSEQ + l0 + l] = x + dd;
        ls += (double)dd * (double)dd;
    }
    if (tid < 16) out[QELEMS + 1 + (size_t)(t0 + tid)] = (float)sidx[tid];
#pragma unroll
    for (int o = 16; o; o >>= 1) ls += __shfl_down_sync(0xffffffffu, ls, o);
    if ((tid & 31) == 0) wsum[tid >> 5] = ls;
    __syncthreads();
    if (tid == 0) {
        double s = 0.0;
#pragma unroll
        for (int w = 0; w < 8; w++) s += wsum[w];
        atomicAdd(&g_loss, s);
    }
}

__global__ void loss_final_kernel(float* __restrict__ out) {
    out[QELEMS] = (float)(1.25 * g_loss / (double)QELEMS);
}

// ---------------------------------------------------------------------------
extern "C" void kernel_launch(void* const* d_in, const int* in_sizes, int n_in,
                              void* d_out, int out_size) {
    const float* inputs = (const float*)d_in[0];
    const float* emb    = (const float*)d_in[1];
    const float* proj   = (const float*)d_in[2];
    float* out = (float*)d_out;

    static bool attr_done = false;
    if (!attr_done) {
        cudaFuncSetAttribute(filter_kernel,
                             cudaFuncAttributeMaxDynamicSharedMemorySize, SMEM_REQ);
        attr_done = true;
    }

    zero_loss_kernel<<<1, 1>>>();
    transpose_kernel<<<dim3(LSEQ / 32, DIM / 32, BATCH), dim3(32, 8)>>>(inputs);
    codebook_gemm_kernel<<<dim3(DIM / 128, NUM_E / 128), 256>>>(emb, proj);
    rownorm_kernel<<<(NTOK * 32) / 256, 256>>>(0);
    rownorm_kernel<<<(NUM_E * 32) / 256, 256>>>(1);
    filter_kernel<<<NTOK / 128, 256, SMEM_REQ>>>();
    rescore_kernel<<<NTOK / 256, 256>>>();
    gather_out_kernel<<<NTOK / 16, 256>>>(inputs, out);
    loss_final_kernel<<<1, 1>>>(out);
}

// round 6
// speedup vs baseline: 1.3944x; 1.3944x over previous
#include <cuda_runtime.h>
#include <cuda_bf16.h>
#include <math_constants.h>
#include <cstdint>

#define NUM_E 8192
#define DIM   512
#define BATCH 8
#define LSEQ  4096
#define NTOK  (BATCH * LSEQ)          // 32768
#define QELEMS ((size_t)BATCH * DIM * LSEQ)  // 16777216
#define CAP   32
#define TAU   4e-4f

// ---------------- scratch (device globals; no runtime allocation) ----------
__device__ __align__(256) float         g_xT[(size_t)NTOK * DIM];
__device__ __align__(256) __nv_bfloat16 g_xbf[(size_t)NTOK * DIM];
__device__ __align__(256) float         g_codebook[(size_t)NUM_E * DIM];
__device__ __align__(256) __nv_bfloat16 g_cbf[(size_t)NUM_E * DIM];
__device__ float  g_xnorm[NTOK];
__device__ float  g_cnorm[NUM_E];
__device__ int    g_cand[(size_t)NTOK * CAP];
__device__ int    g_cnt[NTOK];
__device__ int    g_argmin[NTOK];
__device__ double g_loss;

// ---------------- PTX helpers (baseline ISA only; no tcgen05) ---------------
__device__ __forceinline__ uint32_t smem_u32(const void* p) {
    uint32_t a;
    asm("{ .reg .u64 t; cvta.to.shared.u64 t, %1; cvt.u32.u64 %0, t; }"
        : "=r"(a) : "l"(p));
    return a;
}
__device__ __forceinline__ void cp16(uint32_t dst, const void* src) {
    asm volatile("cp.async.cg.shared.global [%0], [%1], 16;" :: "r"(dst), "l"(src));
}
#define CP_COMMIT() asm volatile("cp.async.commit_group;" ::: "memory")
#define CP_WAIT1()  asm volatile("cp.async.wait_group 1;" ::: "memory")

__device__ __forceinline__ void ldm_x4(uint32_t& r0, uint32_t& r1, uint32_t& r2,
                                       uint32_t& r3, uint32_t addr) {
    asm volatile("ldmatrix.sync.aligned.m8n8.x4.shared.b16 {%0,%1,%2,%3}, [%4];"
                 : "=r"(r0), "=r"(r1), "=r"(r2), "=r"(r3) : "r"(addr));
}
__device__ __forceinline__ void mma_bf16(float& c0, float& c1, float& c2, float& c3,
                                         uint32_t a0, uint32_t a1, uint32_t a2,
                                         uint32_t a3, uint32_t b0, uint32_t b1) {
    asm volatile("mma.sync.aligned.m16n8k16.row.col.f32.bf16.bf16.f32 "
                 "{%0,%1,%2,%3}, {%4,%5,%6,%7}, {%8,%9}, {%0,%1,%2,%3};"
                 : "+f"(c0), "+f"(c1), "+f"(c2), "+f"(c3)
                 : "r"(a0), "r"(a1), "r"(a2), "r"(a3), "r"(b0), "r"(b1));
}
// order-preserving float<->uint map for unsigned atomicMin
__device__ __forceinline__ uint32_t fmap(float f) {
    uint32_t u = __float_as_uint(f);
    return (u & 0x80000000u) ? ~u : (u | 0x80000000u);
}
__device__ __forceinline__ float funmap(uint32_t u) {
    return __uint_as_float((u & 0x80000000u) ? (u & 0x7FFFFFFFu) : ~u);
}

// ---------------------------------------------------------------------------
__global__ void zero_loss_kernel() { g_loss = 0.0; }

// inputs [B, D, L] -> g_xT / g_xbf [(b*L + l), d]
__global__ void transpose_kernel(const float* __restrict__ in) {
    __shared__ float tile[32][33];
    int b  = blockIdx.z;
    int d0 = blockIdx.y * 32;
    int l0 = blockIdx.x * 32;
    int tx = threadIdx.x, ty = threadIdx.y;
    const float* src = in + (size_t)b * DIM * LSEQ;
#pragma unroll
    for (int i = 0; i < 4; i++)
        tile[ty + i * 8][tx] = src[(size_t)(d0 + ty + i * 8) * LSEQ + l0 + tx];
    __syncthreads();
#pragma unroll
    for (int i = 0; i < 4; i++) {
        int l = l0 + ty + i * 8;
        float v = tile[tx][ty + i * 8];
        size_t idx = (size_t)(b * LSEQ + l) * DIM + d0 + tx;
        g_xT[idx] = v;
        g_xbf[idx] = __float2bfloat16(v);
    }
}

// codebook[k][d] = sum_j emb[k][j] * proj[d][j]  (128x128 tile, 8x8/thread)
__global__ __launch_bounds__(256, 2) void codebook_gemm_kernel(
    const float* __restrict__ E, const float* __restrict__ P) {
    __shared__ float As[8][128];
    __shared__ float Bs[8][128];
    int tid = threadIdx.x;
    int ty = tid >> 4, tx = tid & 15;
    int k0 = blockIdx.y * 128;
    int d0 = blockIdx.x * 128;
    int srow = tid >> 2;
    int scol = (tid & 3) * 2;
    float acc[8][8];
#pragma unroll
    for (int i = 0; i < 8; i++)
#pragma unroll
        for (int j = 0; j < 8; j++) acc[i][j] = 0.f;

    for (int j0 = 0; j0 < DIM; j0 += 8) {
#pragma unroll
        for (int i = 0; i < 2; i++) {
            int m = srow + i * 64;
            float2 av = *(const float2*)&E[(size_t)(k0 + m) * DIM + j0 + scol];
            float2 bv = *(const float2*)&P[(size_t)(d0 + m) * DIM + j0 + scol];
            As[scol][m] = av.x; As[scol + 1][m] = av.y;
            Bs[scol][m] = bv.x; Bs[scol + 1][m] = bv.y;
        }
        __syncthreads();
#pragma unroll
        for (int j = 0; j < 8; j++) {
            float a[8], bb[8];
#pragma unroll
            for (int i = 0; i < 8; i++) a[i]  = As[j][ty * 8 + i];
#pragma unroll
            for (int i = 0; i < 8; i++) bb[i] = Bs[j][tx * 8 + i];
#pragma unroll
            for (int i = 0; i < 8; i++)
#pragma unroll
                for (int jj = 0; jj < 8; jj++) acc[i][jj] += a[i] * bb[jj];
        }
        __syncthreads();
    }
#pragma unroll
    for (int i = 0; i < 8; i++)
#pragma unroll
        for (int jj = 0; jj < 8; jj++) {
            float v = acc[i][jj];
            size_t idx = (size_t)(k0 + ty * 8 + i) * DIM + d0 + tx * 8 + jj;
            g_codebook[idx] = v;
            g_cbf[idx] = __float2bfloat16(v);
        }
}

__global__ void rownorm_kernel(int which) {
    int warp = (blockIdx.x * blockDim.x + threadIdx.x) >> 5;
    int lane = threadIdx.x & 31;
    int rows = which ? NUM_E : NTOK;
    if (warp >= rows) return;
    const float* r = (which ? g_codebook : g_xT) + (size_t)warp * DIM;
    float s = 0.f;
#pragma unroll
    for (int i = 0; i < DIM / 32; i++) { float v = r[lane + i * 32]; s += v * v; }
#pragma unroll
    for (int o = 16; o; o >>= 1) s += __shfl_down_sync(0xffffffffu, s, o);
    if (lane == 0) (which ? g_cnorm : g_xnorm)[warp] = s;
}

// ------------------- HMMA (mma.sync) candidate-filter kernel ----------------
#define OFF_X    0          // 128 rows x 1024B (swizzled)            131072
#define OFF_C    131072     // 3 x 16384 (128 codes x 128B, swizzled)  49152
#define OFF_CAND 180224     // 128 x CAP x 4                           16384
#define OFF_CNT  196608     // 128 x 4
#define OFF_RMIN 197120     // 128 x 4
#define OFF_CNS  197632     // 128 x 4
#define SMEM_REQ 198144

__device__ __forceinline__ void prefetch_stage(int s, int tid, uint32_t cbase) {
    if (s < 512) {
        int nc = s >> 3, dc = s & 7, buf = s % 3;
        int row = tid >> 1, half = tid & 1;
        const char* srow = (const char*)g_cbf
            + (size_t)(nc * 128 + row) * 1024 + dc * 128 + half * 64;
        uint32_t drow = cbase + buf * 16384 + row * 128;
        uint32_t xr = (uint32_t)((row & 7) << 4);
#pragma unroll
        for (int i = 0; i < 4; i++) {
            uint32_t b = half * 64 + i * 16;
            cp16(drow + (b ^ xr), srow + i * 16);
        }
    }
    CP_COMMIT();
}

__global__ __launch_bounds__(256, 1) void filter_kernel() {
    extern __shared__ __align__(16) char sm[];
    uint32_t smb = smem_u32(sm);
    int tid  = threadIdx.x;
    int wid  = tid >> 5;
    int lane = tid & 31;
    int m0   = blockIdx.x * 128;
    int mw = wid & 1;          // M-split: 2 x 64
    int nw = wid >> 1;         // N-split: 4 x 32

    uint32_t xbase = smb + OFF_X;
    uint32_t cbase = smb + OFF_C;
    int*      cand_s = (int*)(sm + OFF_CAND);
    uint32_t* cnt_s  = (uint32_t*)(sm + OFF_CNT);
    uint32_t* rmin_s = (uint32_t*)(sm + OFF_RMIN);
    float*    cn_s   = (float*)(sm + OFF_CNS);

    if (tid < 128) { cnt_s[tid] = 0; rmin_s[tid] = 0xFF800000u; } // map(+inf)

    // ---- stage X tile (swizzled bf16) ----
    {
        int row = tid >> 1, half = tid & 1;
        const uint4* srow = (const uint4*)((const char*)g_xbf
                            + (size_t)(m0 + row) * 1024 + half * 512);
        char* drow = sm + OFF_X + row * 1024;
        uint32_t xr = (uint32_t)((row & 7) << 4);
#pragma unroll
        for (int j = 0; j < 32; j++) {
            uint4 v = srow[j];
            uint32_t b = half * 512 + j * 16;
            *(uint4*)(drow + (b ^ xr)) = v;
        }
    }

    // ---- precomputed ldmatrix addressing ----
    uint32_t aRow[4], aXor[4];
#pragma unroll
    for (int mf = 0; mf < 4; mf++) {
        int r = mw * 64 + mf * 16 + (lane & 15);
        aRow[mf] = (uint32_t)(r * 1024);
        aXor[mf] = (uint32_t)((r & 7) << 4);
    }
    uint32_t aK = ((lane >> 4) & 1) * 16;
    uint32_t bRow[2], bXor[2];
    {
        int n16 = (lane & 7) + ((lane >> 4) & 1) * 8;
#pragma unroll
        for (int g = 0; g < 2; g++) {
            int r = nw * 32 + g * 16 + n16;
            bRow[g] = (uint32_t)(r * 128);
            bXor[g] = (uint32_t)((r & 7) << 4);
        }
    }
    uint32_t bK = ((lane >> 3) & 1) * 16;

    float accs[4][4][4];
#pragma unroll
    for (int mf = 0; mf < 4; mf++)
#pragma unroll
        for (int nf = 0; nf < 4; nf++)
#pragma unroll
            for (int v = 0; v < 4; v++) accs[mf][nf][v] = 0.f;

    prefetch_stage(0, tid, cbase);
    prefetch_stage(1, tid, cbase);
    __syncthreads();   // X tile + init visible

    for (int s = 0; s < 512; s++) {
        int nc = s >> 3, dc = s & 7;
        CP_WAIT1();
        __syncthreads();
        if (dc == 0 && tid < 128) cn_s[tid] = __ldg(&g_cnorm[nc * 128 + tid]);
        prefetch_stage(s + 2, tid, cbase);

        uint32_t cb = cbase + (uint32_t)(s % 3) * 16384;
#pragma unroll
        for (int ks = 0; ks < 4; ks++) {
            uint32_t a[4][4];
            uint32_t abyte = (uint32_t)(dc * 128 + ks * 32) + aK;
#pragma unroll
            for (int mf = 0; mf < 4; mf++)
                ldm_x4(a[mf][0], a[mf][1], a[mf][2], a[mf][3],
                       xbase + aRow[mf] + (abyte ^ aXor[mf]));
            uint32_t b[2][4];
            uint32_t bbyte = (uint32_t)(ks * 32) + bK;
#pragma unroll
            for (int g = 0; g < 2; g++)
                ldm_x4(b[g][0], b[g][1], b[g][2], b[g][3],
                       cb + bRow[g] + (bbyte ^ bXor[g]));
#pragma unroll
            for (int mf = 0; mf < 4; mf++)
#pragma unroll
                for (int nf = 0; nf < 4; nf++) {
                    uint32_t b0 = b[nf >> 1][(nf & 1) * 2];
                    uint32_t b1 = b[nf >> 1][(nf & 1) * 2 + 1];
                    mma_bf16(accs[mf][nf][0], accs[mf][nf][1],
                             accs[mf][nf][2], accs[mf][nf][3],
                             a[mf][0], a[mf][1], a[mf][2], a[mf][3], b0, b1);
                }
        }

        if (dc == 7) {
            // ---- Phase A: per-token chunk min -> shared prefix min ----
#pragma unroll
            for (int mf = 0; mf < 4; mf++) {
#pragma unroll
                for (int half = 0; half < 2; half++) {
                    int r = mw * 64 + mf * 16 + (lane >> 2) + half * 8;
                    float lm = CUDART_INF_F;
#pragma unroll
                    for (int nf = 0; nf < 4; nf++) {
                        int c = nw * 32 + nf * 8 + (lane & 3) * 2;
#pragma unroll
                        for (int e = 0; e < 2; e++) {
                            float sv = fmaf(-2.0f, accs[mf][nf][half * 2 + e],
                                            cn_s[c + e]);
                            lm = fminf(lm, sv);
                        }
                    }
                    atomicMin(&rmin_s[r], fmap(lm));
                }
            }
            __syncthreads();  // prefix min (incl. this chunk) visible to all
            // ---- Phase B: append candidates within TAU of prefix min ----
#pragma unroll
            for (int mf = 0; mf < 4; mf++) {
#pragma unroll
                for (int half = 0; half < 2; half++) {
                    int r = mw * 64 + mf * 16 + (lane >> 2) + half * 8;
                    float thr = funmap(rmin_s[r]) + TAU;
#pragma unroll
                    for (int nf = 0; nf < 4; nf++) {
                        int c = nw * 32 + nf * 8 + (lane & 3) * 2;
#pragma unroll
                        for (int e = 0; e < 2; e++) {
                            float sv = fmaf(-2.0f, accs[mf][nf][half * 2 + e],
                                            cn_s[c + e]);
                            if (sv <= thr) {
                                uint32_t slot = atomicAdd(&cnt_s[r], 1u);
                                if (slot < CAP)
                                    cand_s[r * CAP + slot] = nc * 128 + c + e;
                            }
                            accs[mf][nf][half * 2 + e] = 0.f;
                        }
                    }
                }
            }
        }
    }

    __syncthreads();
    if (tid < 128) {
        uint32_t n = cnt_s[tid];
        g_cnt[m0 + tid] = (n > CAP) ? -1 : (int)n;
        int nn = n > CAP ? CAP : (int)n;
        for (int i = 0; i < nn; i++)
            g_cand[(size_t)(m0 + tid) * CAP + i] = cand_s[tid * CAP + i];
    }
}

// exact fp32 rescore (sequential FMA chain); -1 count => full-scan fallback
__global__ __launch_bounds__(256) void rescore_kernel() {
    int t = blockIdx.x * 256 + threadIdx.x;
    float xn = g_xnorm[t];
    int n = g_cnt[t];
    const float4* xr = (const float4*)(g_xT + (size_t)t * DIM);
    float best = CUDART_INF_F;
    int bi = 0;
    int total = (n < 0) ? NUM_E : n;
    for (int i = 0; i < total; i++) {
        int k = (n < 0) ? i : g_cand[(size_t)t * CAP + i];
        const float4* cr = (const float4*)(g_codebook + (size_t)k * DIM);
        float acc = 0.f;
#pragma unroll 8
        for (int v = 0; v < DIM / 4; v++) {
            float4 a = xr[v], b = cr[v];
            acc = fmaf(a.x, b.x, acc);
            acc = fmaf(a.y, b.y, acc);
            acc = fmaf(a.z, b.z, acc);
            acc = fmaf(a.w, b.w, acc);
        }
        float dv = (xn + g_cnorm[k]) - 2.0f * acc;
        if (dv < best || (dv == best && k < bi)) { best = dv; bi = k; }
    }
    g_argmin[t] = bi;
}

// gather codebook rows, write quantized [B,D,L], indices-as-float, loss accum
__global__ __launch_bounds__(256) void gather_out_kernel(
    const float* __restrict__ in, float* __restrict__ out) {
    __shared__ float qs[16][513];
    __shared__ int sidx[16];
    __shared__ double wsum[8];
    int t0 = blockIdx.x * 16;
    int tid = threadIdx.x;
    if (tid < 16) sidx[tid] = g_argmin[t0 + tid];
    __syncthreads();
#pragma unroll
    for (int i = 0; i < 8; i++) {
        int e = tid + i * 256;
        int tok = e >> 7, d4 = e & 127;
        float4 v = *(const float4*)&g_codebook[(size_t)sidx[tok] * DIM + d4 * 4];
        qs[tok][d4 * 4]     = v.x;
        qs[tok][d4 * 4 + 1] = v.y;
        qs[tok][d4 * 4 + 2] = v.z;
        qs[tok][d4 * 4 + 3] = v.w;
    }
    __syncthreads();
    int b  = t0 / LSEQ;
    int l0 = t0 % LSEQ;
    const float* src = in  + (size_t)b * DIM * LSEQ;
    float*       dst = out + (size_t)b * DIM * LSEQ;
    double ls = 0.0;
#pragma unroll
    for (int i = 0; i < 32; i++) {
        int e = tid + i * 256;
        int d = e >> 4, l = e & 15;
        float q = qs[l][d];
        float x = src[(size_t)d * LSEQ + l0 + l];
        float dd = q - x;
        dst[(size_t)d * LSEQ + l0 + l] = x + dd;
        ls += (double)dd * (double)dd;
    }
    if (tid < 16) out[QELEMS + 1 + (size_t)(t0 + tid)] = (float)sidx[tid];
#pragma unroll
    for (int o = 16; o; o >>= 1) ls += __shfl_down_sync(0xffffffffu, ls, o);
    if ((tid & 31) == 0) wsum[tid >> 5] = ls;
    __syncthreads();
    if (tid == 0) {
        double s = 0.0;
#pragma unroll
        for (int w = 0; w < 8; w++) s += wsum[w];
        atomicAdd(&g_loss, s);
    }
}

__global__ void loss_final_kernel(float* __restrict__ out) {
    out[QELEMS] = (float)(1.25 * g_loss / (double)QELEMS);
}

// ---------------------------------------------------------------------------
extern "C" void kernel_launch(void* const* d_in, const int* in_sizes, int n_in,
                              void* d_out, int out_size) {
    const float* inputs = (const float*)d_in[0];
    const float* emb    = (const float*)d_in[1];
    const float* proj   = (const float*)d_in[2];
    float* out = (float*)d_out;

    static bool attr_done = false;
    if (!attr_done) {
        cudaFuncSetAttribute(filter_kernel,
                             cudaFuncAttributeMaxDynamicSharedMemorySize, SMEM_REQ);
        attr_done = true;
    }

    zero_loss_kernel<<<1, 1>>>();
    transpose_kernel<<<dim3(LSEQ / 32, DIM / 32, BATCH), dim3(32, 8)>>>(inputs);
    codebook_gemm_kernel<<<dim3(DIM / 128, NUM_E / 128), 256>>>(emb, proj);
    rownorm_kernel<<<(NTOK * 32) / 256, 256>>>(0);
    rownorm_kernel<<<(NUM_E * 32) / 256, 256>>>(1);
    filter_kernel<<<NTOK / 128, 256, SMEM_REQ>>>();
    rescore_kernel<<<NTOK / 256, 256>>>();
    gather_out_kernel<<<NTOK / 16, 256>>>(inputs, out);
    loss_final_kernel<<<1, 1>>>(out);
}